// round 10
// baseline (speedup 1.0000x reference)
#include <cuda_runtime.h>
#include <cuda_bf16.h>
#include <cuda_fp16.h>
#include <cstdint>
#include <cstddef>

#define NN   8192
#define DF   784
#define DFP  800     // padded K (25 * 32)
#define DEMB 256
#define TK   11
#define TK2  24      // coarse candidate count (margin >> coarse error)
#define NCB  64      // column blocks per row (NN / 128)
#define CAP  512     // survivor buffer capacity

// ---------------- scratch (static device globals; no allocs) ----------------
__device__ float g_sq[NN];                            // correctly-rounded fp32 row norms
__device__ __align__(16) __nv_bfloat16 g_Xb[(size_t)NN * DFP];  // bf16 X, zero-padded
__device__ __align__(16) __half g_D[(size_t)NN * NN]; // fp16 coarse dist (128 MB scratch)
__device__ float g_bmin[(size_t)NN * NCB];            // per-(row, colblock) min (fp16-rounded)
__device__ int   g_idx24[NN * TK2];                   // coarse candidates
__device__ int   g_idx[NN * TK];                      // refined top-11
__device__ int   g_cnt[NN];
__device__ float g_dv[NN];
__device__ float g_G[(size_t)NN * DF];                // gathered dv-weighted rows

__device__ __forceinline__ unsigned smem_u32(const void* p) {
    return (unsigned)__cvta_generic_to_shared(p);
}
__device__ __forceinline__ void cp16(void* smem, const void* gmem) {
    asm volatile("cp.async.cg.shared.global [%0], [%1], 16;\n"
                 :: "r"(smem_u32(smem)), "l"(gmem));
}

// ---------------- 0. convert X -> bf16 (zero-pad K to 800) ----------------
__global__ void conv_kernel(const float* __restrict__ X) {
    int row = blockIdx.x;
    for (int c = threadIdx.x; c < DFP; c += 256) {
        g_Xb[(size_t)row * DFP + c] =
            (c < DF) ? __float2bfloat16_rn(X[(size_t)row * DF + c]) : __float2bfloat16_rn(0.f);
    }
}

// ---------------- 1. row squared norms (correctly rounded) ----------------
__global__ void sq_kernel(const float* __restrict__ X) {
    int row  = blockIdx.x * 8 + (threadIdx.x >> 5);
    int lane = threadIdx.x & 31;
    const float* xr = X + (size_t)row * DF;
    float s = 0.f, c = 0.f;
    for (int k = lane; k < DF; k += 32) {
        float v = xr[k];
        float p = __fmul_rn(v, v);
        float y = __fsub_rn(p, c);
        float t = __fadd_rn(s, y);
        c = __fsub_rn(__fsub_rn(t, s), y);
        s = t;
    }
    double d = (double)s + (double)c;
    #pragma unroll
    for (int o = 16; o; o >>= 1) d += __shfl_xor_sync(0xffffffffu, d, o);
    if (lane == 0) g_sq[row] = (float)d;
}

// ---------------- 2. coarse dist via bf16 HMMA, cp.async double-buffered ----------------
// C = Xb @ Xb^T ; D16[i][j] = fp16(|sq_i + sq_j - 2 C|) ; g_bmin over fp16 values
#define SROW 40   // smem row stride in bf16 elems (80 B -> conflict-free ldmatrix)

__global__ __launch_bounds__(256) void dist_mma() {
    __shared__ __nv_bfloat16 As[2][128 * SROW];
    __shared__ __nv_bfloat16 Bs[2][128 * SROW];
    __shared__ float swm[128][4];

    int tid  = threadIdx.x;
    int warp = tid >> 5, lane = tid & 31;
    int bi = blockIdx.y * 128, bj = blockIdx.x * 128;
    int wm = (warp >> 2) * 64;     // 0 / 64
    int wn = (warp & 3) * 32;      // 0 / 32 / 64 / 96

    float acc[4][4][4];
    #pragma unroll
    for (int m = 0; m < 4; m++)
        #pragma unroll
        for (int n = 0; n < 4; n++)
            #pragma unroll
            for (int r = 0; r < 4; r++) acc[m][n][r] = 0.f;

    const int NT = DFP / 32;   // 25

    // async stage loader: 128x32 bf16 tiles of A and B into buffer b
    auto issue = [&](int kt, int b) {
        #pragma unroll
        for (int l = 0; l < 2; l++) {
            int q = tid + l * 256;
            int row = q >> 2, c = q & 3;
            cp16(&As[b][row * SROW + c * 8],
                 g_Xb + (size_t)(bi + row) * DFP + kt * 32 + c * 8);
            cp16(&Bs[b][row * SROW + c * 8],
                 g_Xb + (size_t)(bj + row) * DFP + kt * 32 + c * 8);
        }
        asm volatile("cp.async.commit_group;\n");
    };

    issue(0, 0);

    for (int kt = 0; kt < NT; kt++) {
        int b = kt & 1;
        if (kt + 1 < NT) {
            issue(kt + 1, b ^ 1);
            asm volatile("cp.async.wait_group 1;\n");
        } else {
            asm volatile("cp.async.wait_group 0;\n");
        }
        __syncthreads();

        #pragma unroll
        for (int ks = 0; ks < 2; ks++) {
            int k0 = ks * 16;
            uint32_t a[4][4];
            #pragma unroll
            for (int mt = 0; mt < 4; mt++) {
                unsigned ad = smem_u32(&As[b][(wm + mt * 16 + (lane & 15)) * SROW
                                             + k0 + ((lane >> 4) << 3)]);
                asm volatile("ldmatrix.sync.aligned.m8n8.x4.shared.b16 {%0,%1,%2,%3}, [%4];"
                             : "=r"(a[mt][0]), "=r"(a[mt][1]), "=r"(a[mt][2]), "=r"(a[mt][3])
                             : "r"(ad));
            }
            uint32_t bf[4][2];
            #pragma unroll
            for (int bt = 0; bt < 2; bt++) {
                int nloc = wn + bt * 16 + ((lane >> 4) << 3) + (lane & 7);
                unsigned ad = smem_u32(&Bs[b][nloc * SROW + k0 + (((lane >> 3) & 1) << 3)]);
                uint32_t r0, r1, r2, r3;
                asm volatile("ldmatrix.sync.aligned.m8n8.x4.shared.b16 {%0,%1,%2,%3}, [%4];"
                             : "=r"(r0), "=r"(r1), "=r"(r2), "=r"(r3) : "r"(ad));
                bf[2 * bt][0] = r0; bf[2 * bt][1] = r1;
                bf[2 * bt + 1][0] = r2; bf[2 * bt + 1][1] = r3;
            }
            #pragma unroll
            for (int mt = 0; mt < 4; mt++)
                #pragma unroll
                for (int nt = 0; nt < 4; nt++) {
                    asm volatile(
                        "mma.sync.aligned.m16n8k16.row.col.f32.bf16.bf16.f32 "
                        "{%0,%1,%2,%3}, {%4,%5,%6,%7}, {%8,%9}, {%0,%1,%2,%3};"
                        : "+f"(acc[mt][nt][0]), "+f"(acc[mt][nt][1]),
                          "+f"(acc[mt][nt][2]), "+f"(acc[mt][nt][3])
                        : "r"(a[mt][0]), "r"(a[mt][1]), "r"(a[mt][2]), "r"(a[mt][3]),
                          "r"(bf[nt][0]), "r"(bf[nt][1]));
                }
        }
        __syncthreads();
    }

    // epilogue: fp16 dist store + per-row min over fp16-rounded values
    int r_in = lane >> 2, cb = (lane & 3) * 2;
    #pragma unroll
    for (int mt = 0; mt < 4; mt++) {
        #pragma unroll
        for (int half = 0; half < 2; half++) {
            int gi = bi + wm + mt * 16 + r_in + half * 8;
            float sqi = g_sq[gi];
            float rmin = 3.4e38f;
            #pragma unroll
            for (int nt = 0; nt < 4; nt++) {
                int gj = bj + wn + nt * 8 + cb;
                float ox = fabsf(sqi + g_sq[gj]     - 2.f * acc[mt][nt][half * 2 + 0]);
                float oy = fabsf(sqi + g_sq[gj + 1] - 2.f * acc[mt][nt][half * 2 + 1]);
                __half2 h2 = __floats2half2_rn(ox, oy);
                *reinterpret_cast<__half2*>(g_D + (size_t)gi * NN + gj) = h2;
                rmin = fminf(rmin, fminf(__low2float(h2), __high2float(h2)));
            }
            rmin = fminf(rmin, __shfl_xor_sync(0xffffffffu, rmin, 1));
            rmin = fminf(rmin, __shfl_xor_sync(0xffffffffu, rmin, 2));
            if ((lane & 3) == 0)
                swm[wm + mt * 16 + r_in + half * 8][warp & 3] = rmin;
        }
    }
    __syncthreads();
    if (tid < 128) {
        float m = fminf(fminf(swm[tid][0], swm[tid][1]),
                        fminf(swm[tid][2], swm[tid][3]));
        g_bmin[(size_t)(bi + tid) * NCB + blockIdx.x] = m;
    }
}

// ---------------- 3. per-row top-24 via threshold filter (fp16 D) ----------------
__global__ __launch_bounds__(256) void topk_fast() {
    int row = blockIdx.x, t = threadIdx.x;
    __shared__ float sb[NCB];
    __shared__ float sT;
    __shared__ int cnt;
    __shared__ unsigned long long buf[CAP];

    if (t < NCB) sb[t] = g_bmin[(size_t)row * NCB + t];
    if (t == 0) cnt = 0;
    __syncthreads();

    // parallel rank-select: T = 24th smallest block-min (strict order via index tiebreak)
    if (t < NCB) {
        float x = sb[t];
        int r = 0;
        #pragma unroll 16
        for (int j = 0; j < NCB; j++)
            r += (sb[j] < x) || (sb[j] == x && j < t);
        if (r == TK2 - 1) sT = x;
    }
    __syncthreads();
    float T = sT;

    // filter: preload 4 x uint4 (32 halfs) per thread, then threshold-test
    const uint4* dr = (const uint4*)(g_D + (size_t)row * NN);
    uint4 w[4];
    #pragma unroll
    for (int i = 0; i < 4; i++) w[i] = dr[t + i * 256];
    #pragma unroll
    for (int i = 0; i < 4; i++) {
        int j0 = (t + i * 256) * 8;
        const __half2* hp = (const __half2*)&w[i];
        #pragma unroll
        for (int q = 0; q < 4; q++) {
            float2 f = __half22float2(hp[q]);
            if (f.x <= T) {
                int p = atomicAdd(&cnt, 1);
                if (p < CAP)
                    buf[p] = ((unsigned long long)__float_as_uint(f.x) << 32)
                             | (unsigned)(j0 + 2 * q);
            }
            if (f.y <= T) {
                int p = atomicAdd(&cnt, 1);
                if (p < CAP)
                    buf[p] = ((unsigned long long)__float_as_uint(f.y) << 32)
                             | (unsigned)(j0 + 2 * q + 1);
            }
        }
    }
    __syncthreads();

    if (t == 0) {
        unsigned long long best[TK2];
        #pragma unroll
        for (int k = 0; k < TK2; k++) best[k] = ~0ull;
        if (cnt <= CAP) {
            int n = cnt;
            for (int i = 0; i < n; i++) {
                unsigned long long x = buf[i];
                if (x < best[TK2 - 1]) {
                    int k = TK2 - 1;
                    while (k > 0 && best[k - 1] > x) { best[k] = best[k - 1]; k--; }
                    best[k] = x;
                }
            }
        } else {
            // fallback (practically unreachable): full serial scan of fp16 row
            const __half* drh = g_D + (size_t)row * NN;
            for (int j = 0; j < NN; j++) {
                float d = __half2float(drh[j]);
                unsigned long long x =
                    ((unsigned long long)__float_as_uint(d) << 32) | (unsigned)j;
                if (x < best[TK2 - 1]) {
                    int k = TK2 - 1;
                    while (k > 0 && best[k - 1] > x) { best[k] = best[k - 1]; k--; }
                    best[k] = x;
                }
            }
        }
        #pragma unroll
        for (int k = 0; k < TK2; k++) g_idx24[row * TK2 + k] = (int)(unsigned)best[k];
    }
}

// ---------------- 4. refine: exact dists with ref's rounding chain, pick top-11 ----------------
__global__ __launch_bounds__(128) void refine_kernel(const float* __restrict__ X) {
    int row = blockIdx.x;
    int wid = threadIdx.x >> 5, lane = threadIdx.x & 31;
    __shared__ unsigned long long keys[TK2];
    __shared__ int cand[TK2];
    if (threadIdx.x < TK2) cand[threadIdx.x] = g_idx24[row * TK2 + threadIdx.x];
    __syncthreads();

    float sqi = g_sq[row];
    const float* xi = X + (size_t)row * DF;

    for (int k4 = wid; k4 < TK2; k4 += 4) {
        int j = cand[k4];
        const float* xj = X + (size_t)j * DF;
        float s = 0.f, c = 0.f;
        for (int k = lane; k < DF; k += 32) {
            float p = __fmul_rn(xi[k], xj[k]);
            float y = __fsub_rn(p, c);
            float t = __fadd_rn(s, y);
            c = __fsub_rn(__fsub_rn(t, s), y);
            s = t;
        }
        double d = (double)s + (double)c;
        #pragma unroll
        for (int o = 16; o; o >>= 1) d += __shfl_xor_sync(0xffffffffu, d, o);
        if (lane == 0) {
            float dotf = (float)d;
            float t1 = __fadd_rn(sqi, g_sq[j]);
            float t3 = fabsf(__fsub_rn(t1, __fmul_rn(2.0f, dotf)));
            keys[k4] = ((unsigned long long)__float_as_uint(t3) << 32) | (unsigned)j;
        }
    }
    __syncthreads();

    if (threadIdx.x == 0) {
        unsigned long long a[TK2];
        #pragma unroll
        for (int i = 0; i < TK2; i++) a[i] = keys[i];
        #pragma unroll
        for (int i = 1; i < TK2; i++) {
            unsigned long long v = a[i];
            int k = i - 1;
            while (k >= 0 && a[k] > v) { a[k + 1] = a[k]; k--; }
            a[k + 1] = v;
        }
        #pragma unroll
        for (int k = 0; k < TK; k++) g_idx[row * TK + k] = (int)(unsigned)a[k];
    }
}

// ---------------- 5. degrees / zero / scatter / gather / gemm / E ----------------
__global__ void zero_cnt() {
    int t = blockIdx.x * 256 + threadIdx.x;
    if (t < NN) g_cnt[t] = 0;
}
__global__ void count_kernel() {
    int t = blockIdx.x * 256 + threadIdx.x;
    if (t < NN * TK) atomicAdd(&g_cnt[g_idx[t]], 1);
}
__global__ void dv_kernel() {
    int t = blockIdx.x * 256 + threadIdx.x;
    if (t < NN) g_dv[t] = 1.0f / sqrtf((float)g_cnt[t]);
}

__global__ void zero_kernel(float4* __restrict__ p, size_t n4) {
    size_t t = (size_t)blockIdx.x * blockDim.x + threadIdx.x;
    size_t stride = (size_t)gridDim.x * blockDim.x;
    float4 z = make_float4(0.f, 0.f, 0.f, 0.f);
    for (size_t i = t; i < n4; i += stride) p[i] = z;
}

__global__ void scatterH(float* __restrict__ H) {
    int t = blockIdx.x * 256 + threadIdx.x;
    if (t < NN * TK) {
        int i = t / TK;
        int r = g_idx[t];
        H[(size_t)r * NN + i] = 1.0f;
    }
}

__global__ __launch_bounds__(256) void gather_kernel(const float* __restrict__ X) {
    int i = blockIdx.x;
    __shared__ int   sidx[TK];
    __shared__ float sdv[TK];
    if (threadIdx.x < TK) {
        int r = g_idx[i * TK + threadIdx.x];
        sidx[threadIdx.x] = r;
        sdv[threadIdx.x]  = g_dv[r];
    }
    __syncthreads();
    for (int c = threadIdx.x; c < DF; c += 256) {
        float s = 0.f;
        #pragma unroll
        for (int k = 0; k < TK; k++)
            s = fmaf(sdv[k], X[(size_t)sidx[k] * DF + c], s);
        g_G[(size_t)i * DF + c] = s;
    }
}

#define BK 16
#define SPAD 4
__global__ __launch_bounds__(256) void out_gemm(const float* __restrict__ theta,
                                                float* __restrict__ Xout) {
    __shared__ float As[BK][64 + SPAD];
    __shared__ float Bs[BK][64 + SPAD];
    int tid = threadIdx.x;
    int tx = tid & 15, ty = tid >> 4;
    int bi = blockIdx.y * 64, bj = blockIdx.x * 64;

    float acc[4][4];
    #pragma unroll
    for (int m = 0; m < 4; m++)
        #pragma unroll
        for (int n = 0; n < 4; n++) acc[m][n] = 0.f;

    for (int k0 = 0; k0 < DF; k0 += BK) {
        {
            int row = tid >> 2, c4 = (tid & 3) * 4;
            float4 v = *reinterpret_cast<const float4*>(g_G + (size_t)(bi + row) * DF + k0 + c4);
            As[c4 + 0][row] = v.x; As[c4 + 1][row] = v.y;
            As[c4 + 2][row] = v.z; As[c4 + 3][row] = v.w;
            int kr = tid >> 4, n4 = (tid & 15) * 4;
            float4 w = *reinterpret_cast<const float4*>(theta + (size_t)(k0 + kr) * DEMB + bj + n4);
            Bs[kr][n4 + 0] = w.x; Bs[kr][n4 + 1] = w.y;
            Bs[kr][n4 + 2] = w.z; Bs[kr][n4 + 3] = w.w;
        }
        __syncthreads();
        #pragma unroll
        for (int kk = 0; kk < BK; kk++) {
            float a[4], b[4];
            #pragma unroll
            for (int m = 0; m < 4; m++) a[m] = As[kk][ty * 4 + m];
            #pragma unroll
            for (int n = 0; n < 4; n++) b[n] = Bs[kk][tx * 4 + n];
            #pragma unroll
            for (int m = 0; m < 4; m++)
                #pragma unroll
                for (int n = 0; n < 4; n++) acc[m][n] = fmaf(a[m], b[n], acc[m][n]);
        }
        __syncthreads();
    }
    const float de = 0.30151134457776363f;  // 11^-0.5
    #pragma unroll
    for (int m = 0; m < 4; m++) {
        int i = bi + ty * 4 + m;
        float4 o;
        o.x = de * acc[m][0]; o.y = de * acc[m][1];
        o.z = de * acc[m][2]; o.w = de * acc[m][3];
        *reinterpret_cast<float4*>(Xout + (size_t)i * DEMB + bj + tx * 4) = o;
    }
}

__global__ void scatterE(const float* __restrict__ Xout, float* __restrict__ E) {
    int j = blockIdx.x;
    int c = threadIdx.x;
    float v = Xout[(size_t)j * DEMB + c];
    #pragma unroll
    for (int k = 0; k < TK; k++) {
        int r = __ldg(&g_idx[j * TK + k]);
        atomicAdd(E + (size_t)r * DEMB + c, v);
    }
}
__global__ void scaleE(float* __restrict__ E) {
    int t = blockIdx.x * 256 + threadIdx.x;
    const float de = 0.30151134457776363f;
    int i = t >> 8;
    E[t] *= g_dv[i] * de;
}

// ---------------- launch ----------------
extern "C" void kernel_launch(void* const* d_in, const int* in_sizes, int n_in,
                              void* d_out, int out_size) {
    const float* X     = (const float*)d_in[0];
    const float* theta = (const float*)d_in[1];
    float* out  = (float*)d_out;
    float* Xout = out;                                // [8192, 256]
    float* E    = out + (size_t)NN * DEMB;            // [8192, 256]
    float* H    = out + 2 * (size_t)NN * DEMB;        // [8192, 8192]

    conv_kernel<<<NN, 256>>>(X);
    sq_kernel<<<NN / 8, 256>>>(X);
    dist_mma<<<dim3(NN / 128, NN / 128), 256>>>();    // cp.async HMMA, fp16 D + blockmins
    topk_fast<<<NN, 256>>>();
    refine_kernel<<<NN, 128>>>(X);                    // exact-emulated top-11
    zero_cnt<<<NN / 256, 256>>>();
    count_kernel<<<(NN * TK + 255) / 256, 256>>>();
    dv_kernel<<<NN / 256, 256>>>();
    zero_kernel<<<2048, 256>>>((float4*)H, (size_t)NN * NN / 4);
    scatterH<<<(NN * TK + 255) / 256, 256>>>(H);
    gather_kernel<<<NN, 256>>>(X);
    out_gemm<<<dim3(DEMB / 64, NN / 64), 256>>>(theta, Xout);
    zero_kernel<<<256, 256>>>((float4*)E, (size_t)NN * DEMB / 4);
    scatterE<<<NN, 256>>>(Xout, E);
    scaleE<<<NN * DEMB / 256, 256>>>(E);
}

// round 11
// speedup vs baseline: 1.4578x; 1.4578x over previous
#include <cuda_runtime.h>
#include <cuda_bf16.h>
#include <cstdint>
#include <cstddef>

#define NN   8192
#define DF   784
#define DFP  800     // padded K (25 * 32)
#define DEMB 256
#define TK   11
#define TK2  24      // coarse candidate count (margin >> bf16 coarse error)
#define NCB  64      // column blocks per row (NN / 128)
#define CAP  512     // survivor buffer capacity

// ---------------- scratch (static device globals; no allocs) ----------------
__device__ float g_sq[NN];                            // correctly-rounded fp32 row norms
__device__ __align__(16) __nv_bfloat16 g_Xb[(size_t)NN * DFP];  // bf16 X, zero-padded
__device__ float g_bmin[(size_t)NN * NCB];            // per-(row, colblock) min dist
__device__ int   g_idx24[NN * TK2];                   // coarse candidates
__device__ int   g_idx[NN * TK];                      // refined top-11
__device__ int   g_cnt[NN];
__device__ float g_dv[NN];
__device__ float g_G[(size_t)NN * DF];                // gathered dv-weighted rows

__device__ __forceinline__ unsigned smem_u32(const void* p) {
    return (unsigned)__cvta_generic_to_shared(p);
}

// ---------------- 0. convert X -> bf16 (zero-pad K to 800) ----------------
__global__ void conv_kernel(const float* __restrict__ X) {
    int row = blockIdx.x;
    for (int c = threadIdx.x; c < DFP; c += 256) {
        g_Xb[(size_t)row * DFP + c] =
            (c < DF) ? __float2bfloat16_rn(X[(size_t)row * DF + c]) : __float2bfloat16_rn(0.f);
    }
}

// ---------------- 1. row squared norms (correctly rounded) ----------------
__global__ void sq_kernel(const float* __restrict__ X) {
    int row  = blockIdx.x * 8 + (threadIdx.x >> 5);
    int lane = threadIdx.x & 31;
    const float* xr = X + (size_t)row * DF;
    float s = 0.f, c = 0.f;
    for (int k = lane; k < DF; k += 32) {
        float v = xr[k];
        float p = __fmul_rn(v, v);
        float y = __fsub_rn(p, c);
        float t = __fadd_rn(s, y);
        c = __fsub_rn(__fsub_rn(t, s), y);
        s = t;
    }
    double d = (double)s + (double)c;
    #pragma unroll
    for (int o = 16; o; o >>= 1) d += __shfl_xor_sync(0xffffffffu, d, o);
    if (lane == 0) g_sq[row] = (float)d;
}

// ---------------- 2. coarse dist via bf16 tensor cores + per-row block-min ----------------
// C = Xb @ Xb^T ; D[i][j] = |sq_i + sq_j - 2 C[i][j]| ; g_bmin[i][bx] = min_j-in-block D
#define SROW 40   // smem row stride in bf16 elems (80 B -> conflict-free ldmatrix)

__global__ __launch_bounds__(256) void dist_mma(float* __restrict__ D) {
    __shared__ __nv_bfloat16 As[128 * SROW];
    __shared__ __nv_bfloat16 Bs[128 * SROW];
    __shared__ float swm[128][4];

    int tid  = threadIdx.x;
    int warp = tid >> 5, lane = tid & 31;
    int bi = blockIdx.y * 128, bj = blockIdx.x * 128;
    int wm = (warp >> 2) * 64;     // 0 / 64
    int wn = (warp & 3) * 32;      // 0 / 32 / 64 / 96

    float acc[4][4][4];
    #pragma unroll
    for (int m = 0; m < 4; m++)
        #pragma unroll
        for (int n = 0; n < 4; n++)
            #pragma unroll
            for (int r = 0; r < 4; r++) acc[m][n][r] = 0.f;

    for (int kt = 0; kt < DFP / 32; kt++) {
        #pragma unroll
        for (int l = 0; l < 2; l++) {
            int q = tid + l * 256;
            int row = q >> 2, ch = q & 3;
            const int4* sa = (const int4*)(g_Xb + (size_t)(bi + row) * DFP + kt * 32 + ch * 8);
            *(int4*)(As + row * SROW + ch * 8) = *sa;
            const int4* sb = (const int4*)(g_Xb + (size_t)(bj + row) * DFP + kt * 32 + ch * 8);
            *(int4*)(Bs + row * SROW + ch * 8) = *sb;
        }
        __syncthreads();

        #pragma unroll
        for (int ks = 0; ks < 2; ks++) {
            int k0 = ks * 16;
            uint32_t a[4][4];
            #pragma unroll
            for (int mt = 0; mt < 4; mt++) {
                unsigned ad = smem_u32(As + (wm + mt * 16 + (lane & 15)) * SROW
                                          + k0 + ((lane >> 4) << 3));
                asm volatile("ldmatrix.sync.aligned.m8n8.x4.shared.b16 {%0,%1,%2,%3}, [%4];"
                             : "=r"(a[mt][0]), "=r"(a[mt][1]), "=r"(a[mt][2]), "=r"(a[mt][3])
                             : "r"(ad));
            }
            uint32_t b[4][2];
            #pragma unroll
            for (int bt = 0; bt < 2; bt++) {
                int nloc = wn + bt * 16 + ((lane >> 4) << 3) + (lane & 7);
                unsigned ad = smem_u32(Bs + nloc * SROW + k0 + (((lane >> 3) & 1) << 3));
                uint32_t r0, r1, r2, r3;
                asm volatile("ldmatrix.sync.aligned.m8n8.x4.shared.b16 {%0,%1,%2,%3}, [%4];"
                             : "=r"(r0), "=r"(r1), "=r"(r2), "=r"(r3) : "r"(ad));
                b[2 * bt][0] = r0; b[2 * bt][1] = r1;
                b[2 * bt + 1][0] = r2; b[2 * bt + 1][1] = r3;
            }
            #pragma unroll
            for (int mt = 0; mt < 4; mt++)
                #pragma unroll
                for (int nt = 0; nt < 4; nt++) {
                    asm volatile(
                        "mma.sync.aligned.m16n8k16.row.col.f32.bf16.bf16.f32 "
                        "{%0,%1,%2,%3}, {%4,%5,%6,%7}, {%8,%9}, {%0,%1,%2,%3};"
                        : "+f"(acc[mt][nt][0]), "+f"(acc[mt][nt][1]),
                          "+f"(acc[mt][nt][2]), "+f"(acc[mt][nt][3])
                        : "r"(a[mt][0]), "r"(a[mt][1]), "r"(a[mt][2]), "r"(a[mt][3]),
                          "r"(b[nt][0]), "r"(b[nt][1]));
                }
        }
        __syncthreads();
    }

    // epilogue: dist = |sq_i + sq_j - 2*acc| ; also per-row min over this block
    int r_in = lane >> 2, cb = (lane & 3) * 2;
    #pragma unroll
    for (int mt = 0; mt < 4; mt++) {
        #pragma unroll
        for (int half = 0; half < 2; half++) {
            int gi = bi + wm + mt * 16 + r_in + half * 8;
            float sqi = g_sq[gi];
            float rmin = 3.4e38f;
            #pragma unroll
            for (int nt = 0; nt < 4; nt++) {
                int gj = bj + wn + nt * 8 + cb;
                float2 o;
                o.x = fabsf(sqi + g_sq[gj]     - 2.f * acc[mt][nt][half * 2 + 0]);
                o.y = fabsf(sqi + g_sq[gj + 1] - 2.f * acc[mt][nt][half * 2 + 1]);
                rmin = fminf(rmin, fminf(o.x, o.y));
                *reinterpret_cast<float2*>(D + (size_t)gi * NN + gj) = o;
            }
            rmin = fminf(rmin, __shfl_xor_sync(0xffffffffu, rmin, 1));
            rmin = fminf(rmin, __shfl_xor_sync(0xffffffffu, rmin, 2));
            if ((lane & 3) == 0)
                swm[wm + mt * 16 + r_in + half * 8][warp & 3] = rmin;
        }
    }
    __syncthreads();
    if (tid < 128) {
        float m = fminf(fminf(swm[tid][0], swm[tid][1]),
                        fminf(swm[tid][2], swm[tid][3]));
        g_bmin[(size_t)(bi + tid) * NCB + blockIdx.x] = m;
    }
}

// ---------------- 3. per-row top-24 via threshold filter (batched preload) ----------------
// T = 24th smallest of the row's 64 block-mins (each an actual row value at a
// distinct position => valid upper bound on the 24th order statistic).
__global__ __launch_bounds__(256) void topk_fast(const float* __restrict__ D) {
    int row = blockIdx.x, t = threadIdx.x;
    __shared__ float sb[NCB];
    __shared__ float sT;
    __shared__ int cnt;
    __shared__ unsigned long long buf[CAP];

    if (t < NCB) sb[t] = g_bmin[(size_t)row * NCB + t];
    if (t == 0) cnt = 0;
    __syncthreads();

    // parallel rank-select: T = 24th smallest block-min (strict order via index tiebreak)
    if (t < NCB) {
        float x = sb[t];
        int r = 0;
        #pragma unroll 16
        for (int j = 0; j < NCB; j++)
            r += (sb[j] < x) || (sb[j] == x && j < t);
        if (r == TK2 - 1) sT = x;
    }
    __syncthreads();
    float T = sT;

    // preload all 8 float4s (128 B / thread) before filtering: MLP=8
    const float4* dr4 = (const float4*)(D + (size_t)row * NN);
    float4 w[8];
    #pragma unroll
    for (int i = 0; i < 8; i++) w[i] = dr4[t + i * 256];

    #pragma unroll
    for (int i = 0; i < 8; i++) {
        int j0 = (t + i * 256) * 4;
        float vals[4] = {w[i].x, w[i].y, w[i].z, w[i].w};
        #pragma unroll
        for (int q = 0; q < 4; q++) {
            if (vals[q] <= T) {
                int p = atomicAdd(&cnt, 1);
                if (p < CAP)
                    buf[p] = ((unsigned long long)__float_as_uint(vals[q]) << 32)
                             | (unsigned)(j0 + q);
            }
        }
    }
    __syncthreads();

    if (t == 0) {
        unsigned long long best[TK2];
        #pragma unroll
        for (int k = 0; k < TK2; k++) best[k] = ~0ull;
        if (cnt <= CAP) {
            int n = cnt;
            for (int i = 0; i < n; i++) {
                unsigned long long x = buf[i];
                if (x < best[TK2 - 1]) {
                    int k = TK2 - 1;
                    while (k > 0 && best[k - 1] > x) { best[k] = best[k - 1]; k--; }
                    best[k] = x;
                }
            }
        } else {
            // fallback (practically unreachable): full serial scan, still exact
            const float* dr = D + (size_t)row * NN;
            for (int j = 0; j < NN; j++) {
                unsigned long long x =
                    ((unsigned long long)__float_as_uint(dr[j]) << 32) | (unsigned)j;
                if (x < best[TK2 - 1]) {
                    int k = TK2 - 1;
                    while (k > 0 && best[k - 1] > x) { best[k] = best[k - 1]; k--; }
                    best[k] = x;
                }
            }
        }
        #pragma unroll
        for (int k = 0; k < TK2; k++) g_idx24[row * TK2 + k] = (int)(unsigned)best[k];
    }
}

// ---------------- 4. refine: exact dists with ref's rounding chain, pick top-11 ----------------
__global__ __launch_bounds__(128) void refine_kernel(const float* __restrict__ X) {
    int row = blockIdx.x;
    int wid = threadIdx.x >> 5, lane = threadIdx.x & 31;
    __shared__ unsigned long long keys[TK2];
    __shared__ int cand[TK2];
    if (threadIdx.x < TK2) cand[threadIdx.x] = g_idx24[row * TK2 + threadIdx.x];
    __syncthreads();

    float sqi = g_sq[row];
    const float* xi = X + (size_t)row * DF;

    for (int k4 = wid; k4 < TK2; k4 += 4) {
        int j = cand[k4];
        const float* xj = X + (size_t)j * DF;
        float s = 0.f, c = 0.f;
        for (int k = lane; k < DF; k += 32) {
            float p = __fmul_rn(xi[k], xj[k]);
            float y = __fsub_rn(p, c);
            float t = __fadd_rn(s, y);
            c = __fsub_rn(__fsub_rn(t, s), y);
            s = t;
        }
        double d = (double)s + (double)c;
        #pragma unroll
        for (int o = 16; o; o >>= 1) d += __shfl_xor_sync(0xffffffffu, d, o);
        if (lane == 0) {
            float dotf = (float)d;
            float t1 = __fadd_rn(sqi, g_sq[j]);
            float t3 = fabsf(__fsub_rn(t1, __fmul_rn(2.0f, dotf)));
            keys[k4] = ((unsigned long long)__float_as_uint(t3) << 32) | (unsigned)j;
        }
    }
    __syncthreads();

    if (threadIdx.x == 0) {
        unsigned long long a[TK2];
        #pragma unroll
        for (int i = 0; i < TK2; i++) a[i] = keys[i];
        #pragma unroll
        for (int i = 1; i < TK2; i++) {
            unsigned long long v = a[i];
            int k = i - 1;
            while (k >= 0 && a[k] > v) { a[k + 1] = a[k]; k--; }
            a[k + 1] = v;
        }
        #pragma unroll
        for (int k = 0; k < TK; k++) g_idx[row * TK + k] = (int)(unsigned)a[k];
    }
}

// ---------------- 5. vertex degrees ----------------
__global__ void zero_cnt() {
    int t = blockIdx.x * 256 + threadIdx.x;
    if (t < NN) g_cnt[t] = 0;
}
__global__ void count_kernel() {
    int t = blockIdx.x * 256 + threadIdx.x;
    if (t < NN * TK) atomicAdd(&g_cnt[g_idx[t]], 1);
}
__global__ void dv_kernel() {
    int t = blockIdx.x * 256 + threadIdx.x;
    if (t < NN) g_dv[t] = 1.0f / sqrtf((float)g_cnt[t]);
}

// ---------------- zero fill ----------------
__global__ void zero_kernel(float4* __restrict__ p, size_t n4) {
    size_t t = (size_t)blockIdx.x * blockDim.x + threadIdx.x;
    size_t stride = (size_t)gridDim.x * blockDim.x;
    float4 z = make_float4(0.f, 0.f, 0.f, 0.f);
    for (size_t i = t; i < n4; i += stride) p[i] = z;
}

// ---------------- 6. H scatter: H[idx[i][k]][i] = 1 ----------------
__global__ void scatterH(float* __restrict__ H) {
    int t = blockIdx.x * 256 + threadIdx.x;
    if (t < NN * TK) {
        int i = t / TK;
        int r = g_idx[t];
        H[(size_t)r * NN + i] = 1.0f;
    }
}

// ---------------- 7. gather: G[i] = sum_k dv[idx]*X[idx] ----------------
__global__ __launch_bounds__(256) void gather_kernel(const float* __restrict__ X) {
    int i = blockIdx.x;
    __shared__ int   sidx[TK];
    __shared__ float sdv[TK];
    if (threadIdx.x < TK) {
        int r = g_idx[i * TK + threadIdx.x];
        sidx[threadIdx.x] = r;
        sdv[threadIdx.x]  = g_dv[r];
    }
    __syncthreads();
    for (int c = threadIdx.x; c < DF; c += 256) {
        float s = 0.f;
        #pragma unroll
        for (int k = 0; k < TK; k++)
            s = fmaf(sdv[k], X[(size_t)sidx[k] * DF + c], s);
        g_G[(size_t)i * DF + c] = s;
    }
}

// ---------------- 8. X_out = de * G @ theta   (M=8192, N=256, K=784) ----------------
#define BK 16
#define SPAD 4
__global__ __launch_bounds__(256) void out_gemm(const float* __restrict__ theta,
                                                float* __restrict__ Xout) {
    __shared__ float As[BK][64 + SPAD];
    __shared__ float Bs[BK][64 + SPAD];
    int tid = threadIdx.x;
    int tx = tid & 15, ty = tid >> 4;
    int bi = blockIdx.y * 64, bj = blockIdx.x * 64;

    float acc[4][4];
    #pragma unroll
    for (int m = 0; m < 4; m++)
        #pragma unroll
        for (int n = 0; n < 4; n++) acc[m][n] = 0.f;

    for (int k0 = 0; k0 < DF; k0 += BK) {
        {
            int row = tid >> 2, c4 = (tid & 3) * 4;
            float4 v = *reinterpret_cast<const float4*>(g_G + (size_t)(bi + row) * DF + k0 + c4);
            As[c4 + 0][row] = v.x; As[c4 + 1][row] = v.y;
            As[c4 + 2][row] = v.z; As[c4 + 3][row] = v.w;
            int kr = tid >> 4, n4 = (tid & 15) * 4;
            float4 w = *reinterpret_cast<const float4*>(theta + (size_t)(k0 + kr) * DEMB + bj + n4);
            Bs[kr][n4 + 0] = w.x; Bs[kr][n4 + 1] = w.y;
            Bs[kr][n4 + 2] = w.z; Bs[kr][n4 + 3] = w.w;
        }
        __syncthreads();
        #pragma unroll
        for (int kk = 0; kk < BK; kk++) {
            float a[4], b[4];
            #pragma unroll
            for (int m = 0; m < 4; m++) a[m] = As[kk][ty * 4 + m];
            #pragma unroll
            for (int n = 0; n < 4; n++) b[n] = Bs[kk][tx * 4 + n];
            #pragma unroll
            for (int m = 0; m < 4; m++)
                #pragma unroll
                for (int n = 0; n < 4; n++) acc[m][n] = fmaf(a[m], b[n], acc[m][n]);
        }
        __syncthreads();
    }
    const float de = 0.30151134457776363f;  // 11^-0.5
    #pragma unroll
    for (int m = 0; m < 4; m++) {
        int i = bi + ty * 4 + m;
        float4 o;
        o.x = de * acc[m][0]; o.y = de * acc[m][1];
        o.z = de * acc[m][2]; o.w = de * acc[m][3];
        *reinterpret_cast<float4*>(Xout + (size_t)i * DEMB + bj + tx * 4) = o;
    }
}

// ---------------- 9. E = dv * de * scatter-add of X_out ----------------
__global__ void scatterE(const float* __restrict__ Xout, float* __restrict__ E) {
    int j = blockIdx.x;
    int c = threadIdx.x;
    float v = Xout[(size_t)j * DEMB + c];
    #pragma unroll
    for (int k = 0; k < TK; k++) {
        int r = __ldg(&g_idx[j * TK + k]);
        atomicAdd(E + (size_t)r * DEMB + c, v);
    }
}
__global__ void scaleE(float* __restrict__ E) {
    int t = blockIdx.x * 256 + threadIdx.x;
    const float de = 0.30151134457776363f;
    int i = t >> 8;
    E[t] *= g_dv[i] * de;
}

// ---------------- launch ----------------
extern "C" void kernel_launch(void* const* d_in, const int* in_sizes, int n_in,
                              void* d_out, int out_size) {
    const float* X     = (const float*)d_in[0];
    const float* theta = (const float*)d_in[1];
    float* out  = (float*)d_out;
    float* Xout = out;                                // [8192, 256]
    float* E    = out + (size_t)NN * DEMB;            // [8192, 256]
    float* H    = out + 2 * (size_t)NN * DEMB;        // [8192, 8192] (dist scratch first)

    conv_kernel<<<NN, 256>>>(X);
    sq_kernel<<<NN / 8, 256>>>(X);
    dist_mma<<<dim3(NN / 128, NN / 128), 256>>>(H);       // bf16 HMMA coarse dist + blockmins
    topk_fast<<<NN, 256>>>(H);
    refine_kernel<<<NN, 128>>>(X);                        // exact-emulated top-11
    zero_cnt<<<NN / 256, 256>>>();
    count_kernel<<<(NN * TK + 255) / 256, 256>>>();
    dv_kernel<<<NN / 256, 256>>>();
    zero_kernel<<<2048, 256>>>((float4*)H, (size_t)NN * NN / 4);
    scatterH<<<(NN * TK + 255) / 256, 256>>>(H);
    gather_kernel<<<NN, 256>>>(X);
    out_gemm<<<dim3(DEMB / 64, NN / 64), 256>>>(theta, Xout);
    zero_kernel<<<256, 256>>>((float4*)E, (size_t)NN * DEMB / 4);
    scatterE<<<NN, 256>>>(Xout, E);
    scaleE<<<NN * DEMB / 256, 256>>>(E);
}

// round 12
// speedup vs baseline: 1.6230x; 1.1133x over previous
#include <cuda_runtime.h>
#include <cuda_bf16.h>
#include <cstdint>
#include <cstddef>

#define NN   8192
#define DF   784
#define DFP  800     // padded K (25 * 32)
#define DEMB 256
#define TK   11
#define TK2  24      // coarse candidate count (margin >> bf16 coarse error)
#define NCB  64      // column blocks per row (NN / 128)
#define CAP  512     // survivor buffer capacity
#define NTILES 2080  // upper-triangle 128x128 tiles: 64*65/2

// ---------------- scratch (static device globals; no allocs) ----------------
__device__ float g_sq[NN];                            // correctly-rounded fp32 row norms
__device__ __align__(16) __nv_bfloat16 g_Xb[(size_t)NN * DFP];  // bf16 X, zero-padded
__device__ float g_bmin[(size_t)NN * NCB];            // per-(row, colblock) min dist
__device__ int   g_idx24[NN * TK2];                   // coarse candidates
__device__ int   g_idx[NN * TK];                      // refined top-11
__device__ int   g_cnt[NN];
__device__ float g_dv[NN];
__device__ float g_G[(size_t)NN * DF];                // gathered dv-weighted rows

__device__ __forceinline__ unsigned smem_u32(const void* p) {
    return (unsigned)__cvta_generic_to_shared(p);
}

// ---------------- 0. convert X -> bf16 (zero-pad K to 800) ----------------
__global__ void conv_kernel(const float* __restrict__ X) {
    int row = blockIdx.x;
    for (int c = threadIdx.x; c < DFP; c += 256) {
        g_Xb[(size_t)row * DFP + c] =
            (c < DF) ? __float2bfloat16_rn(X[(size_t)row * DF + c]) : __float2bfloat16_rn(0.f);
    }
}

// ---------------- 1. row squared norms (correctly rounded) ----------------
__global__ void sq_kernel(const float* __restrict__ X) {
    int row  = blockIdx.x * 8 + (threadIdx.x >> 5);
    int lane = threadIdx.x & 31;
    const float* xr = X + (size_t)row * DF;
    float s = 0.f, c = 0.f;
    for (int k = lane; k < DF; k += 32) {
        float v = xr[k];
        float p = __fmul_rn(v, v);
        float y = __fsub_rn(p, c);
        float t = __fadd_rn(s, y);
        c = __fsub_rn(__fsub_rn(t, s), y);
        s = t;
    }
    double d = (double)s + (double)c;
    #pragma unroll
    for (int o = 16; o; o >>= 1) d += __shfl_xor_sync(0xffffffffu, d, o);
    if (lane == 0) g_sq[row] = (float)d;
}

// ---------------- 2. coarse dist: upper-triangle HMMA + mirror store ----------------
// One MMA pass over tiles (by <= bx). Direct store D[bi..][bj..] + transposed
// mirror store D[bj..][bi..] via padded smem tile. Block-mins for both sides.
#define SROW 40           // smem row stride in bf16 elems (80 B, conflict-free ldmatrix)
#define TPAD 129          // transpose tile stride in floats (odd -> conflict-free)
#define DSMEM (128 * TPAD * 4)   // 66048 B dynamic smem (aliases As/Bs region)

__global__ __launch_bounds__(256) void dist_mma(float* __restrict__ D) {
    extern __shared__ char dsm[];
    __nv_bfloat16* As = (__nv_bfloat16*)dsm;          // 128*SROW*2 = 10240 B
    __nv_bfloat16* Bs = As + 128 * SROW;              // +10240 B
    float* tile = (float*)dsm;                        // reused for transpose (66048 B)
    __shared__ float swm[128][4];
    __shared__ float scm[128][2];

    // linear block id -> upper-triangle (by, bx), bx >= by
    int t = blockIdx.x;
    int by = (int)(64.5f - sqrtf(64.5f * 64.5f - 2.0f * (float)t));
    while ((by + 1) * 64 - ((by + 1) * by) / 2 <= t) by++;
    while (by * 64 - (by * (by - 1)) / 2 > t) by--;
    int bx = by + (t - (by * 64 - (by * (by - 1)) / 2));

    int tid  = threadIdx.x;
    int warp = tid >> 5, lane = tid & 31;
    int bi = by * 128, bj = bx * 128;
    int wm = (warp >> 2) * 64;     // 0 / 64
    int wn = (warp & 3) * 32;      // 0 / 32 / 64 / 96
    bool offdiag = (bi != bj);

    float acc[4][4][4];
    #pragma unroll
    for (int m = 0; m < 4; m++)
        #pragma unroll
        for (int n = 0; n < 4; n++)
            #pragma unroll
            for (int r = 0; r < 4; r++) acc[m][n][r] = 0.f;

    for (int kt = 0; kt < DFP / 32; kt++) {
        #pragma unroll
        for (int l = 0; l < 2; l++) {
            int q = tid + l * 256;
            int row = q >> 2, ch = q & 3;
            const int4* sa = (const int4*)(g_Xb + (size_t)(bi + row) * DFP + kt * 32 + ch * 8);
            *(int4*)(As + row * SROW + ch * 8) = *sa;
            const int4* sb = (const int4*)(g_Xb + (size_t)(bj + row) * DFP + kt * 32 + ch * 8);
            *(int4*)(Bs + row * SROW + ch * 8) = *sb;
        }
        __syncthreads();

        #pragma unroll
        for (int ks = 0; ks < 2; ks++) {
            int k0 = ks * 16;
            uint32_t a[4][4];
            #pragma unroll
            for (int mt = 0; mt < 4; mt++) {
                unsigned ad = smem_u32(As + (wm + mt * 16 + (lane & 15)) * SROW
                                          + k0 + ((lane >> 4) << 3));
                asm volatile("ldmatrix.sync.aligned.m8n8.x4.shared.b16 {%0,%1,%2,%3}, [%4];"
                             : "=r"(a[mt][0]), "=r"(a[mt][1]), "=r"(a[mt][2]), "=r"(a[mt][3])
                             : "r"(ad));
            }
            uint32_t b[4][2];
            #pragma unroll
            for (int bt = 0; bt < 2; bt++) {
                int nloc = wn + bt * 16 + ((lane >> 4) << 3) + (lane & 7);
                unsigned ad = smem_u32(Bs + nloc * SROW + k0 + (((lane >> 3) & 1) << 3));
                uint32_t r0, r1, r2, r3;
                asm volatile("ldmatrix.sync.aligned.m8n8.x4.shared.b16 {%0,%1,%2,%3}, [%4];"
                             : "=r"(r0), "=r"(r1), "=r"(r2), "=r"(r3) : "r"(ad));
                b[2 * bt][0] = r0; b[2 * bt][1] = r1;
                b[2 * bt + 1][0] = r2; b[2 * bt + 1][1] = r3;
            }
            #pragma unroll
            for (int mt = 0; mt < 4; mt++)
                #pragma unroll
                for (int nt = 0; nt < 4; nt++) {
                    asm volatile(
                        "mma.sync.aligned.m16n8k16.row.col.f32.bf16.bf16.f32 "
                        "{%0,%1,%2,%3}, {%4,%5,%6,%7}, {%8,%9}, {%0,%1,%2,%3};"
                        : "+f"(acc[mt][nt][0]), "+f"(acc[mt][nt][1]),
                          "+f"(acc[mt][nt][2]), "+f"(acc[mt][nt][3])
                        : "r"(a[mt][0]), "r"(a[mt][1]), "r"(a[mt][2]), "r"(a[mt][3]),
                          "r"(b[nt][0]), "r"(b[nt][1]));
                }
        }
        __syncthreads();
    }

    // epilogue: dist in regs; direct store + row-min; col-min; smem transpose tile
    int r_in = lane >> 2, cb = (lane & 3) * 2;
    #pragma unroll
    for (int mt = 0; mt < 4; mt++) {
        #pragma unroll
        for (int half = 0; half < 2; half++) {
            int rloc = wm + mt * 16 + r_in + half * 8;
            int gi = bi + rloc;
            float sqi = g_sq[gi];
            float rmin = 3.4e38f;
            #pragma unroll
            for (int nt = 0; nt < 4; nt++) {
                int cloc = wn + nt * 8 + cb;
                int gj = bj + cloc;
                float2 o;
                o.x = fabsf(sqi + g_sq[gj]     - 2.f * acc[mt][nt][half * 2 + 0]);
                o.y = fabsf(sqi + g_sq[gj + 1] - 2.f * acc[mt][nt][half * 2 + 1]);
                acc[mt][nt][half * 2 + 0] = o.x;
                acc[mt][nt][half * 2 + 1] = o.y;
                rmin = fminf(rmin, fminf(o.x, o.y));
                *reinterpret_cast<float2*>(D + (size_t)gi * NN + gj) = o;
            }
            rmin = fminf(rmin, __shfl_xor_sync(0xffffffffu, rmin, 1));
            rmin = fminf(rmin, __shfl_xor_sync(0xffffffffu, rmin, 2));
            if ((lane & 3) == 0)
                swm[rloc][warp & 3] = rmin;
        }
    }

    if (offdiag) {
        // col-min (mirror-row min): reduce over mt in regs, then across r_in lanes
        #pragma unroll
        for (int nt = 0; nt < 4; nt++) {
            float v0 = 3.4e38f, v1 = 3.4e38f;
            #pragma unroll
            for (int mt = 0; mt < 4; mt++) {
                v0 = fminf(v0, fminf(acc[mt][nt][0], acc[mt][nt][2]));
                v1 = fminf(v1, fminf(acc[mt][nt][1], acc[mt][nt][3]));
            }
            #pragma unroll
            for (int o = 4; o <= 16; o <<= 1) {
                v0 = fminf(v0, __shfl_xor_sync(0xffffffffu, v0, o));
                v1 = fminf(v1, __shfl_xor_sync(0xffffffffu, v1, o));
            }
            if (r_in == 0) {
                scm[wn + nt * 8 + cb + 0][wm >> 6] = v0;
                scm[wn + nt * 8 + cb + 1][wm >> 6] = v1;
            }
        }
        // stage tile into smem for transposed mirror store
        #pragma unroll
        for (int mt = 0; mt < 4; mt++)
            #pragma unroll
            for (int half = 0; half < 2; half++) {
                int rloc = wm + mt * 16 + r_in + half * 8;
                #pragma unroll
                for (int nt = 0; nt < 4; nt++) {
                    int cloc = wn + nt * 8 + cb;
                    tile[rloc * TPAD + cloc]     = acc[mt][nt][half * 2 + 0];
                    tile[rloc * TPAD + cloc + 1] = acc[mt][nt][half * 2 + 1];
                }
            }
    }
    __syncthreads();

    if (tid < 128) {
        float m = fminf(fminf(swm[tid][0], swm[tid][1]),
                        fminf(swm[tid][2], swm[tid][3]));
        g_bmin[(size_t)(bi + tid) * NCB + bx] = m;
        if (offdiag) {
            float c = fminf(scm[tid][0], scm[tid][1]);
            g_bmin[(size_t)(bj + tid) * NCB + by] = c;
        }
    }

    if (offdiag) {
        // mirror store: D[bj + r][bi + c] = tile[c][r]; coalesced STG, conflict-free LDS
        for (int idx = tid; idx < 128 * 128; idx += 256) {
            int r = idx >> 7, c = idx & 127;
            D[(size_t)(bj + r) * NN + bi + c] = tile[c * TPAD + r];
        }
    }
}

// ---------------- 3. per-row top-24 via threshold filter (batched preload) ----------------
__global__ __launch_bounds__(256) void topk_fast(const float* __restrict__ D) {
    int row = blockIdx.x, t = threadIdx.x;
    __shared__ float sb[NCB];
    __shared__ float sT;
    __shared__ int cnt;
    __shared__ unsigned long long buf[CAP];

    if (t < NCB) sb[t] = g_bmin[(size_t)row * NCB + t];
    if (t == 0) cnt = 0;
    __syncthreads();

    // parallel rank-select: T = 24th smallest block-min (strict order via index tiebreak)
    if (t < NCB) {
        float x = sb[t];
        int r = 0;
        #pragma unroll 16
        for (int j = 0; j < NCB; j++)
            r += (sb[j] < x) || (sb[j] == x && j < t);
        if (r == TK2 - 1) sT = x;
    }
    __syncthreads();
    float T = sT;

    // preload all 8 float4s (128 B / thread) before filtering: MLP=8
    const float4* dr4 = (const float4*)(D + (size_t)row * NN);
    float4 w[8];
    #pragma unroll
    for (int i = 0; i < 8; i++) w[i] = dr4[t + i * 256];

    #pragma unroll
    for (int i = 0; i < 8; i++) {
        int j0 = (t + i * 256) * 4;
        float vals[4] = {w[i].x, w[i].y, w[i].z, w[i].w};
        #pragma unroll
        for (int q = 0; q < 4; q++) {
            if (vals[q] <= T) {
                int p = atomicAdd(&cnt, 1);
                if (p < CAP)
                    buf[p] = ((unsigned long long)__float_as_uint(vals[q]) << 32)
                             | (unsigned)(j0 + q);
            }
        }
    }
    __syncthreads();

    if (t == 0) {
        unsigned long long best[TK2];
        #pragma unroll
        for (int k = 0; k < TK2; k++) best[k] = ~0ull;
        if (cnt <= CAP) {
            int n = cnt;
            for (int i = 0; i < n; i++) {
                unsigned long long x = buf[i];
                if (x < best[TK2 - 1]) {
                    int k = TK2 - 1;
                    while (k > 0 && best[k - 1] > x) { best[k] = best[k - 1]; k--; }
                    best[k] = x;
                }
            }
        } else {
            // fallback (practically unreachable): full serial scan, still exact
            const float* dr = D + (size_t)row * NN;
            for (int j = 0; j < NN; j++) {
                unsigned long long x =
                    ((unsigned long long)__float_as_uint(dr[j]) << 32) | (unsigned)j;
                if (x < best[TK2 - 1]) {
                    int k = TK2 - 1;
                    while (k > 0 && best[k - 1] > x) { best[k] = best[k - 1]; k--; }
                    best[k] = x;
                }
            }
        }
        #pragma unroll
        for (int k = 0; k < TK2; k++) g_idx24[row * TK2 + k] = (int)(unsigned)best[k];
    }
}

// ---------------- 4. refine: exact dists with ref's rounding chain, pick top-11 ----------------
__global__ __launch_bounds__(128) void refine_kernel(const float* __restrict__ X) {
    int row = blockIdx.x;
    int wid = threadIdx.x >> 5, lane = threadIdx.x & 31;
    __shared__ unsigned long long keys[TK2];
    __shared__ int cand[TK2];
    if (threadIdx.x < TK2) cand[threadIdx.x] = g_idx24[row * TK2 + threadIdx.x];
    __syncthreads();

    float sqi = g_sq[row];
    const float* xi = X + (size_t)row * DF;

    for (int k4 = wid; k4 < TK2; k4 += 4) {
        int j = cand[k4];
        const float* xj = X + (size_t)j * DF;
        float s = 0.f, c = 0.f;
        for (int k = lane; k < DF; k += 32) {
            float p = __fmul_rn(xi[k], xj[k]);
            float y = __fsub_rn(p, c);
            float t = __fadd_rn(s, y);
            c = __fsub_rn(__fsub_rn(t, s), y);
            s = t;
        }
        double d = (double)s + (double)c;
        #pragma unroll
        for (int o = 16; o; o >>= 1) d += __shfl_xor_sync(0xffffffffu, d, o);
        if (lane == 0) {
            float dotf = (float)d;
            float t1 = __fadd_rn(sqi, g_sq[j]);
            float t3 = fabsf(__fsub_rn(t1, __fmul_rn(2.0f, dotf)));
            keys[k4] = ((unsigned long long)__float_as_uint(t3) << 32) | (unsigned)j;
        }
    }
    __syncthreads();

    if (threadIdx.x == 0) {
        unsigned long long a[TK2];
        #pragma unroll
        for (int i = 0; i < TK2; i++) a[i] = keys[i];
        #pragma unroll
        for (int i = 1; i < TK2; i++) {
            unsigned long long v = a[i];
            int k = i - 1;
            while (k >= 0 && a[k] > v) { a[k + 1] = a[k]; k--; }
            a[k + 1] = v;
        }
        #pragma unroll
        for (int k = 0; k < TK; k++) g_idx[row * TK + k] = (int)(unsigned)a[k];
    }
}

// ---------------- 5. vertex degrees ----------------
__global__ void zero_cnt() {
    int t = blockIdx.x * 256 + threadIdx.x;
    if (t < NN) g_cnt[t] = 0;
}
__global__ void count_kernel() {
    int t = blockIdx.x * 256 + threadIdx.x;
    if (t < NN * TK) atomicAdd(&g_cnt[g_idx[t]], 1);
}
__global__ void dv_kernel() {
    int t = blockIdx.x * 256 + threadIdx.x;
    if (t < NN) g_dv[t] = 1.0f / sqrtf((float)g_cnt[t]);
}

// ---------------- zero fill ----------------
__global__ void zero_kernel(float4* __restrict__ p, size_t n4) {
    size_t t = (size_t)blockIdx.x * blockDim.x + threadIdx.x;
    size_t stride = (size_t)gridDim.x * blockDim.x;
    float4 z = make_float4(0.f, 0.f, 0.f, 0.f);
    for (size_t i = t; i < n4; i += stride) p[i] = z;
}

// ---------------- 6. H scatter: H[idx[i][k]][i] = 1 ----------------
__global__ void scatterH(float* __restrict__ H) {
    int t = blockIdx.x * 256 + threadIdx.x;
    if (t < NN * TK) {
        int i = t / TK;
        int r = g_idx[t];
        H[(size_t)r * NN + i] = 1.0f;
    }
}

// ---------------- 7. gather: G[i] = sum_k dv[idx]*X[idx] ----------------
__global__ __launch_bounds__(256) void gather_kernel(const float* __restrict__ X) {
    int i = blockIdx.x;
    __shared__ int   sidx[TK];
    __shared__ float sdv[TK];
    if (threadIdx.x < TK) {
        int r = g_idx[i * TK + threadIdx.x];
        sidx[threadIdx.x] = r;
        sdv[threadIdx.x]  = g_dv[r];
    }
    __syncthreads();
    for (int c = threadIdx.x; c < DF; c += 256) {
        float s = 0.f;
        #pragma unroll
        for (int k = 0; k < TK; k++)
            s = fmaf(sdv[k], X[(size_t)sidx[k] * DF + c], s);
        g_G[(size_t)i * DF + c] = s;
    }
}

// ---------------- 8. X_out = de * G @ theta   (M=8192, N=256, K=784) ----------------
#define BK 16
#define SPAD 4
__global__ __launch_bounds__(256) void out_gemm(const float* __restrict__ theta,
                                                float* __restrict__ Xout) {
    __shared__ float As[BK][64 + SPAD];
    __shared__ float Bs[BK][64 + SPAD];
    int tid = threadIdx.x;
    int tx = tid & 15, ty = tid >> 4;
    int bi = blockIdx.y * 64, bj = blockIdx.x * 64;

    float acc[4][4];
    #pragma unroll
    for (int m = 0; m < 4; m++)
        #pragma unroll
        for (int n = 0; n < 4; n++) acc[m][n] = 0.f;

    for (int k0 = 0; k0 < DF; k0 += BK) {
        {
            int row = tid >> 2, c4 = (tid & 3) * 4;
            float4 v = *reinterpret_cast<const float4*>(g_G + (size_t)(bi + row) * DF + k0 + c4);
            As[c4 + 0][row] = v.x; As[c4 + 1][row] = v.y;
            As[c4 + 2][row] = v.z; As[c4 + 3][row] = v.w;
            int kr = tid >> 4, n4 = (tid & 15) * 4;
            float4 w = *reinterpret_cast<const float4*>(theta + (size_t)(k0 + kr) * DEMB + bj + n4);
            Bs[kr][n4 + 0] = w.x; Bs[kr][n4 + 1] = w.y;
            Bs[kr][n4 + 2] = w.z; Bs[kr][n4 + 3] = w.w;
        }
        __syncthreads();
        #pragma unroll
        for (int kk = 0; kk < BK; kk++) {
            float a[4], b[4];
            #pragma unroll
            for (int m = 0; m < 4; m++) a[m] = As[kk][ty * 4 + m];
            #pragma unroll
            for (int n = 0; n < 4; n++) b[n] = Bs[kk][tx * 4 + n];
            #pragma unroll
            for (int m = 0; m < 4; m++)
                #pragma unroll
                for (int n = 0; n < 4; n++) acc[m][n] = fmaf(a[m], b[n], acc[m][n]);
        }
        __syncthreads();
    }
    const float de = 0.30151134457776363f;  // 11^-0.5
    #pragma unroll
    for (int m = 0; m < 4; m++) {
        int i = bi + ty * 4 + m;
        float4 o;
        o.x = de * acc[m][0]; o.y = de * acc[m][1];
        o.z = de * acc[m][2]; o.w = de * acc[m][3];
        *reinterpret_cast<float4*>(Xout + (size_t)i * DEMB + bj + tx * 4) = o;
    }
}

// ---------------- 9. E = dv * de * scatter-add of X_out ----------------
__global__ void scatterE(const float* __restrict__ Xout, float* __restrict__ E) {
    int j = blockIdx.x;
    int c = threadIdx.x;
    float v = Xout[(size_t)j * DEMB + c];
    #pragma unroll
    for (int k = 0; k < TK; k++) {
        int r = __ldg(&g_idx[j * TK + k]);
        atomicAdd(E + (size_t)r * DEMB + c, v);
    }
}
__global__ void scaleE(float* __restrict__ E) {
    int t = blockIdx.x * 256 + threadIdx.x;
    const float de = 0.30151134457776363f;
    int i = t >> 8;
    E[t] *= g_dv[i] * de;
}

// ---------------- launch ----------------
extern "C" void kernel_launch(void* const* d_in, const int* in_sizes, int n_in,
                              void* d_out, int out_size) {
    const float* X     = (const float*)d_in[0];
    const float* theta = (const float*)d_in[1];
    float* out  = (float*)d_out;
    float* Xout = out;                                // [8192, 256]
    float* E    = out + (size_t)NN * DEMB;            // [8192, 256]
    float* H    = out + 2 * (size_t)NN * DEMB;        // [8192, 8192] (dist scratch first)

    static bool attr_set = false;
    if (!attr_set) {
        cudaFuncSetAttribute(dist_mma, cudaFuncAttributeMaxDynamicSharedMemorySize, DSMEM);
        attr_set = true;
    }

    conv_kernel<<<NN, 256>>>(X);
    sq_kernel<<<NN / 8, 256>>>(X);
    dist_mma<<<NTILES, 256, DSMEM>>>(H);                  // upper-tri HMMA + mirror store
    topk_fast<<<NN, 256>>>(H);
    refine_kernel<<<NN, 128>>>(X);                        // exact-emulated top-11
    zero_cnt<<<NN / 256, 256>>>();
    count_kernel<<<(NN * TK + 255) / 256, 256>>>();
    dv_kernel<<<NN / 256, 256>>>();
    zero_kernel<<<2048, 256>>>((float4*)H, (size_t)NN * NN / 4);
    scatterH<<<(NN * TK + 255) / 256, 256>>>(H);
    gather_kernel<<<NN, 256>>>(X);
    out_gemm<<<dim3(DEMB / 64, NN / 64), 256>>>(theta, Xout);
    zero_kernel<<<256, 256>>>((float4*)E, (size_t)NN * DEMB / 4);
    scatterE<<<NN, 256>>>(Xout, E);
    scaleE<<<NN * DEMB / 256, 256>>>(E);
}

// round 13
// speedup vs baseline: 1.8591x; 1.1454x over previous
#include <cuda_runtime.h>
#include <cuda_bf16.h>
#include <cuda_fp16.h>
#include <cstdint>
#include <cstddef>

#define NN   8192
#define DF   784
#define DFP  800     // padded K (25 * 32)
#define DEMB 256
#define TK   11
#define TK2  24      // coarse candidate count (margin >> coarse error)
#define NCB  64      // column blocks per row (NN / 128)
#define CAP  512     // survivor buffer capacity
#define NTILES 2080  // upper-triangle 128x128 tiles: 64*65/2

// ---------------- scratch (static device globals; no allocs) ----------------
__device__ float g_sq[NN];                            // correctly-rounded fp32 row norms
__device__ __align__(16) __nv_bfloat16 g_Xb[(size_t)NN * DFP];  // bf16 X, zero-padded
__device__ __align__(16) __half g_D[(size_t)NN * NN]; // fp16 coarse dist (128 MB)
__device__ float g_bmin[(size_t)NN * NCB];            // per-(row, colblock) min (fp16-rounded)
__device__ int   g_idx24[NN * TK2];                   // coarse candidates
__device__ int   g_idx[NN * TK];                      // refined top-11
__device__ int   g_cnt[NN];
__device__ float g_dv[NN];
__device__ float g_G[(size_t)NN * DF];                // gathered dv-weighted rows

__device__ __forceinline__ unsigned smem_u32(const void* p) {
    return (unsigned)__cvta_generic_to_shared(p);
}

// ---------------- 0. convert X -> bf16 (zero-pad K to 800) ----------------
__global__ void conv_kernel(const float* __restrict__ X) {
    int row = blockIdx.x;
    for (int c = threadIdx.x; c < DFP; c += 256) {
        g_Xb[(size_t)row * DFP + c] =
            (c < DF) ? __float2bfloat16_rn(X[(size_t)row * DF + c]) : __float2bfloat16_rn(0.f);
    }
}

// ---------------- 1. row squared norms (correctly rounded) ----------------
__global__ void sq_kernel(const float* __restrict__ X) {
    int row  = blockIdx.x * 8 + (threadIdx.x >> 5);
    int lane = threadIdx.x & 31;
    const float* xr = X + (size_t)row * DF;
    float s = 0.f, c = 0.f;
    for (int k = lane; k < DF; k += 32) {
        float v = xr[k];
        float p = __fmul_rn(v, v);
        float y = __fsub_rn(p, c);
        float t = __fadd_rn(s, y);
        c = __fsub_rn(__fsub_rn(t, s), y);
        s = t;
    }
    double d = (double)s + (double)c;
    #pragma unroll
    for (int o = 16; o; o >>= 1) d += __shfl_xor_sync(0xffffffffu, d, o);
    if (lane == 0) g_sq[row] = (float)d;
}

// ---------------- 2. coarse dist: upper-triangle HMMA + fp16 store + mirror ----------------
#define SROW 40           // smem row stride in bf16 elems (80 B, conflict-free ldmatrix)
#define TPAD 129          // transpose tile stride in halfs (odd -> conflict-free)
#define DSMEM (128 * TPAD * 2 > 2 * 128 * SROW * 2 ? 128 * TPAD * 2 : 2 * 128 * SROW * 2)

__global__ __launch_bounds__(256) void dist_mma() {
    extern __shared__ char dsm[];
    __nv_bfloat16* As = (__nv_bfloat16*)dsm;          // 128*SROW*2 = 10240 B
    __nv_bfloat16* Bs = As + 128 * SROW;              // +10240 B
    __half* tileh = (__half*)dsm;                     // reused for transpose (33024 B)
    __shared__ float swm[128][4];
    __shared__ float scm[128][2];

    // linear block id -> upper-triangle (by, bx), bx >= by
    int t = blockIdx.x;
    int by = (int)(64.5f - sqrtf(64.5f * 64.5f - 2.0f * (float)t));
    while ((by + 1) * 64 - ((by + 1) * by) / 2 <= t) by++;
    while (by * 64 - (by * (by - 1)) / 2 > t) by--;
    int bx = by + (t - (by * 64 - (by * (by - 1)) / 2));

    int tid  = threadIdx.x;
    int warp = tid >> 5, lane = tid & 31;
    int bi = by * 128, bj = bx * 128;
    int wm = (warp >> 2) * 64;     // 0 / 64
    int wn = (warp & 3) * 32;      // 0 / 32 / 64 / 96
    bool offdiag = (bi != bj);

    float acc[4][4][4];
    #pragma unroll
    for (int m = 0; m < 4; m++)
        #pragma unroll
        for (int n = 0; n < 4; n++)
            #pragma unroll
            for (int r = 0; r < 4; r++) acc[m][n][r] = 0.f;

    for (int kt = 0; kt < DFP / 32; kt++) {
        #pragma unroll
        for (int l = 0; l < 2; l++) {
            int q = tid + l * 256;
            int row = q >> 2, ch = q & 3;
            const int4* sa = (const int4*)(g_Xb + (size_t)(bi + row) * DFP + kt * 32 + ch * 8);
            *(int4*)(As + row * SROW + ch * 8) = *sa;
            const int4* sb = (const int4*)(g_Xb + (size_t)(bj + row) * DFP + kt * 32 + ch * 8);
            *(int4*)(Bs + row * SROW + ch * 8) = *sb;
        }
        __syncthreads();

        #pragma unroll
        for (int ks = 0; ks < 2; ks++) {
            int k0 = ks * 16;
            uint32_t a[4][4];
            #pragma unroll
            for (int mt = 0; mt < 4; mt++) {
                unsigned ad = smem_u32(As + (wm + mt * 16 + (lane & 15)) * SROW
                                          + k0 + ((lane >> 4) << 3));
                asm volatile("ldmatrix.sync.aligned.m8n8.x4.shared.b16 {%0,%1,%2,%3}, [%4];"
                             : "=r"(a[mt][0]), "=r"(a[mt][1]), "=r"(a[mt][2]), "=r"(a[mt][3])
                             : "r"(ad));
            }
            uint32_t b[4][2];
            #pragma unroll
            for (int bt = 0; bt < 2; bt++) {
                int nloc = wn + bt * 16 + ((lane >> 4) << 3) + (lane & 7);
                unsigned ad = smem_u32(Bs + nloc * SROW + k0 + (((lane >> 3) & 1) << 3));
                uint32_t r0, r1, r2, r3;
                asm volatile("ldmatrix.sync.aligned.m8n8.x4.shared.b16 {%0,%1,%2,%3}, [%4];"
                             : "=r"(r0), "=r"(r1), "=r"(r2), "=r"(r3) : "r"(ad));
                b[2 * bt][0] = r0; b[2 * bt][1] = r1;
                b[2 * bt + 1][0] = r2; b[2 * bt + 1][1] = r3;
            }
            #pragma unroll
            for (int mt = 0; mt < 4; mt++)
                #pragma unroll
                for (int nt = 0; nt < 4; nt++) {
                    asm volatile(
                        "mma.sync.aligned.m16n8k16.row.col.f32.bf16.bf16.f32 "
                        "{%0,%1,%2,%3}, {%4,%5,%6,%7}, {%8,%9}, {%0,%1,%2,%3};"
                        : "+f"(acc[mt][nt][0]), "+f"(acc[mt][nt][1]),
                          "+f"(acc[mt][nt][2]), "+f"(acc[mt][nt][3])
                        : "r"(a[mt][0]), "r"(a[mt][1]), "r"(a[mt][2]), "r"(a[mt][3]),
                          "r"(b[nt][0]), "r"(b[nt][1]));
                }
        }
        __syncthreads();
    }

    // epilogue: fp16 dist store + row-min over fp16-rounded values
    int r_in = lane >> 2, cb = (lane & 3) * 2;
    #pragma unroll
    for (int mt = 0; mt < 4; mt++) {
        #pragma unroll
        for (int half_ = 0; half_ < 2; half_++) {
            int rloc = wm + mt * 16 + r_in + half_ * 8;
            int gi = bi + rloc;
            float sqi = g_sq[gi];
            float rmin = 3.4e38f;
            #pragma unroll
            for (int nt = 0; nt < 4; nt++) {
                int cloc = wn + nt * 8 + cb;
                int gj = bj + cloc;
                float ox = fabsf(sqi + g_sq[gj]     - 2.f * acc[mt][nt][half_ * 2 + 0]);
                float oy = fabsf(sqi + g_sq[gj + 1] - 2.f * acc[mt][nt][half_ * 2 + 1]);
                __half2 h2 = __floats2half2_rn(ox, oy);
                *reinterpret_cast<__half2*>(g_D + (size_t)gi * NN + gj) = h2;
                float lx = __low2float(h2), ly = __high2float(h2);
                acc[mt][nt][half_ * 2 + 0] = lx;
                acc[mt][nt][half_ * 2 + 1] = ly;
                rmin = fminf(rmin, fminf(lx, ly));
            }
            rmin = fminf(rmin, __shfl_xor_sync(0xffffffffu, rmin, 1));
            rmin = fminf(rmin, __shfl_xor_sync(0xffffffffu, rmin, 2));
            if ((lane & 3) == 0)
                swm[rloc][warp & 3] = rmin;
        }
    }

    if (offdiag) {
        // col-min (mirror-row min) over fp16-rounded values
        #pragma unroll
        for (int nt = 0; nt < 4; nt++) {
            float v0 = 3.4e38f, v1 = 3.4e38f;
            #pragma unroll
            for (int mt = 0; mt < 4; mt++) {
                v0 = fminf(v0, fminf(acc[mt][nt][0], acc[mt][nt][2]));
                v1 = fminf(v1, fminf(acc[mt][nt][1], acc[mt][nt][3]));
            }
            #pragma unroll
            for (int o = 4; o <= 16; o <<= 1) {
                v0 = fminf(v0, __shfl_xor_sync(0xffffffffu, v0, o));
                v1 = fminf(v1, __shfl_xor_sync(0xffffffffu, v1, o));
            }
            if (r_in == 0) {
                scm[wn + nt * 8 + cb + 0][wm >> 6] = v0;
                scm[wn + nt * 8 + cb + 1][wm >> 6] = v1;
            }
        }
        // stage tile (half) for transposed mirror store
        #pragma unroll
        for (int mt = 0; mt < 4; mt++)
            #pragma unroll
            for (int half_ = 0; half_ < 2; half_++) {
                int rloc = wm + mt * 16 + r_in + half_ * 8;
                #pragma unroll
                for (int nt = 0; nt < 4; nt++) {
                    int cloc = wn + nt * 8 + cb;
                    tileh[rloc * TPAD + cloc]     = __float2half_rn(acc[mt][nt][half_ * 2 + 0]);
                    tileh[rloc * TPAD + cloc + 1] = __float2half_rn(acc[mt][nt][half_ * 2 + 1]);
                }
            }
    }
    __syncthreads();

    if (tid < 128) {
        float m = fminf(fminf(swm[tid][0], swm[tid][1]),
                        fminf(swm[tid][2], swm[tid][3]));
        g_bmin[(size_t)(bi + tid) * NCB + bx] = m;
        if (offdiag) {
            float c = fminf(scm[tid][0], scm[tid][1]);
            g_bmin[(size_t)(bj + tid) * NCB + by] = c;
        }
    }

    if (offdiag) {
        // mirror store: D[bj + r][bi + 2c2 .. +1] = (tile[2c2][r], tile[2c2+1][r])
        for (int idx = tid; idx < 128 * 64; idx += 256) {
            int r = idx >> 6, c2 = idx & 63;
            __half a = tileh[(2 * c2) * TPAD + r];
            __half b = tileh[(2 * c2 + 1) * TPAD + r];
            *reinterpret_cast<__half2*>(g_D + (size_t)(bj + r) * NN + bi + 2 * c2) =
                __halves2half2(a, b);
        }
    }
}

// ---------------- 3. per-row top-24 via threshold filter (fp16, MLP=8) ----------------
__global__ __launch_bounds__(128) void topk_fast() {
    int row = blockIdx.x, t = threadIdx.x;
    __shared__ float sb[NCB];
    __shared__ float sT;
    __shared__ int cnt;
    __shared__ unsigned long long buf[CAP];

    if (t < NCB) sb[t] = g_bmin[(size_t)row * NCB + t];
    if (t == 0) cnt = 0;
    __syncthreads();

    // parallel rank-select: T = 24th smallest block-min
    if (t < NCB) {
        float x = sb[t];
        int r = 0;
        #pragma unroll 16
        for (int j = 0; j < NCB; j++)
            r += (sb[j] < x) || (sb[j] == x && j < t);
        if (r == TK2 - 1) sT = x;
    }
    __syncthreads();
    float T = sT;
    __half2 T2 = __half2half2(__float2half_rn(T));   // T is fp16-representable exactly

    // preload 8 x uint4 (128 B = 64 halfs / thread): MLP=8
    const uint4* dr4 = (const uint4*)(g_D + (size_t)row * NN);
    uint4 w[8];
    #pragma unroll
    for (int i = 0; i < 8; i++) w[i] = dr4[t + i * 128];

    #pragma unroll
    for (int i = 0; i < 8; i++) {
        int base = (t + i * 128) * 8;    // first half index of this uint4
        const __half2* hp = (const __half2*)&w[i];
        #pragma unroll
        for (int q = 0; q < 4; q++) {
            __half2 h = hp[q];
            if (!__hbgt2(h, T2)) {       // at least one lane <= T (rare)
                float fx = __low2float(h), fy = __high2float(h);
                if (fx <= T) {
                    int p = atomicAdd(&cnt, 1);
                    if (p < CAP)
                        buf[p] = ((unsigned long long)__float_as_uint(fx) << 32)
                                 | (unsigned)(base + 2 * q);
                }
                if (fy <= T) {
                    int p = atomicAdd(&cnt, 1);
                    if (p < CAP)
                        buf[p] = ((unsigned long long)__float_as_uint(fy) << 32)
                                 | (unsigned)(base + 2 * q + 1);
                }
            }
        }
    }
    __syncthreads();

    if (t == 0) {
        unsigned long long best[TK2];
        #pragma unroll
        for (int k = 0; k < TK2; k++) best[k] = ~0ull;
        if (cnt <= CAP) {
            int n = cnt;
            for (int i = 0; i < n; i++) {
                unsigned long long x = buf[i];
                if (x < best[TK2 - 1]) {
                    int k = TK2 - 1;
                    while (k > 0 && best[k - 1] > x) { best[k] = best[k - 1]; k--; }
                    best[k] = x;
                }
            }
        } else {
            // fallback (practically unreachable): full serial scan of fp16 row
            const __half* drh = g_D + (size_t)row * NN;
            for (int j = 0; j < NN; j++) {
                float d = __half2float(drh[j]);
                unsigned long long x =
                    ((unsigned long long)__float_as_uint(d) << 32) | (unsigned)j;
                if (x < best[TK2 - 1]) {
                    int k = TK2 - 1;
                    while (k > 0 && best[k - 1] > x) { best[k] = best[k - 1]; k--; }
                    best[k] = x;
                }
            }
        }
        #pragma unroll
        for (int k = 0; k < TK2; k++) g_idx24[row * TK2 + k] = (int)(unsigned)best[k];
    }
}

// ---------------- 4. refine: exact dists with ref's rounding chain, pick top-11 ----------------
__global__ __launch_bounds__(128) void refine_kernel(const float* __restrict__ X) {
    int row = blockIdx.x;
    int wid = threadIdx.x >> 5, lane = threadIdx.x & 31;
    __shared__ unsigned long long keys[TK2];
    __shared__ int cand[TK2];
    if (threadIdx.x < TK2) cand[threadIdx.x] = g_idx24[row * TK2 + threadIdx.x];
    __syncthreads();

    float sqi = g_sq[row];
    const float* xi = X + (size_t)row * DF;

    for (int k4 = wid; k4 < TK2; k4 += 4) {
        int j = cand[k4];
        const float* xj = X + (size_t)j * DF;
        float s = 0.f, c = 0.f;
        for (int k = lane; k < DF; k += 32) {
            float p = __fmul_rn(xi[k], xj[k]);
            float y = __fsub_rn(p, c);
            float t = __fadd_rn(s, y);
            c = __fsub_rn(__fsub_rn(t, s), y);
            s = t;
        }
        double d = (double)s + (double)c;
        #pragma unroll
        for (int o = 16; o; o >>= 1) d += __shfl_xor_sync(0xffffffffu, d, o);
        if (lane == 0) {
            float dotf = (float)d;
            float t1 = __fadd_rn(sqi, g_sq[j]);
            float t3 = fabsf(__fsub_rn(t1, __fmul_rn(2.0f, dotf)));
            keys[k4] = ((unsigned long long)__float_as_uint(t3) << 32) | (unsigned)j;
        }
    }
    __syncthreads();

    if (threadIdx.x == 0) {
        unsigned long long a[TK2];
        #pragma unroll
        for (int i = 0; i < TK2; i++) a[i] = keys[i];
        #pragma unroll
        for (int i = 1; i < TK2; i++) {
            unsigned long long v = a[i];
            int k = i - 1;
            while (k >= 0 && a[k] > v) { a[k + 1] = a[k]; k--; }
            a[k + 1] = v;
        }
        #pragma unroll
        for (int k = 0; k < TK; k++) g_idx[row * TK + k] = (int)(unsigned)a[k];
    }
}

// ---------------- 5. vertex degrees ----------------
__global__ void zero_cnt() {
    int t = blockIdx.x * 256 + threadIdx.x;
    if (t < NN) g_cnt[t] = 0;
}
__global__ void count_kernel() {
    int t = blockIdx.x * 256 + threadIdx.x;
    if (t < NN * TK) atomicAdd(&g_cnt[g_idx[t]], 1);
}
__global__ void dv_kernel() {
    int t = blockIdx.x * 256 + threadIdx.x;
    if (t < NN) g_dv[t] = 1.0f / sqrtf((float)g_cnt[t]);
}

// ---------------- zero fill ----------------
__global__ void zero_kernel(float4* __restrict__ p, size_t n4) {
    size_t t = (size_t)blockIdx.x * blockDim.x + threadIdx.x;
    size_t stride = (size_t)gridDim.x * blockDim.x;
    float4 z = make_float4(0.f, 0.f, 0.f, 0.f);
    for (size_t i = t; i < n4; i += stride) p[i] = z;
}

// ---------------- 6. H scatter: H[idx[i][k]][i] = 1 ----------------
__global__ void scatterH(float* __restrict__ H) {
    int t = blockIdx.x * 256 + threadIdx.x;
    if (t < NN * TK) {
        int i = t / TK;
        int r = g_idx[t];
        H[(size_t)r * NN + i] = 1.0f;
    }
}

// ---------------- 7. gather: G[i] = sum_k dv[idx]*X[idx] ----------------
__global__ __launch_bounds__(256) void gather_kernel(const float* __restrict__ X) {
    int i = blockIdx.x;
    __shared__ int   sidx[TK];
    __shared__ float sdv[TK];
    if (threadIdx.x < TK) {
        int r = g_idx[i * TK + threadIdx.x];
        sidx[threadIdx.x] = r;
        sdv[threadIdx.x]  = g_dv[r];
    }
    __syncthreads();
    for (int c = threadIdx.x; c < DF; c += 256) {
        float s = 0.f;
        #pragma unroll
        for (int k = 0; k < TK; k++)
            s = fmaf(sdv[k], X[(size_t)sidx[k] * DF + c], s);
        g_G[(size_t)i * DF + c] = s;
    }
}

// ---------------- 8. X_out = de * G @ theta   (M=8192, N=256, K=784) ----------------
#define BK 16
#define SPAD 4
__global__ __launch_bounds__(256) void out_gemm(const float* __restrict__ theta,
                                                float* __restrict__ Xout) {
    __shared__ float As[BK][64 + SPAD];
    __shared__ float Bs[BK][64 + SPAD];
    int tid = threadIdx.x;
    int tx = tid & 15, ty = tid >> 4;
    int bi = blockIdx.y * 64, bj = blockIdx.x * 64;

    float acc[4][4];
    #pragma unroll
    for (int m = 0; m < 4; m++)
        #pragma unroll
        for (int n = 0; n < 4; n++) acc[m][n] = 0.f;

    for (int k0 = 0; k0 < DF; k0 += BK) {
        {
            int row = tid >> 2, c4 = (tid & 3) * 4;
            float4 v = *reinterpret_cast<const float4*>(g_G + (size_t)(bi + row) * DF + k0 + c4);
            As[c4 + 0][row] = v.x; As[c4 + 1][row] = v.y;
            As[c4 + 2][row] = v.z; As[c4 + 3][row] = v.w;
            int kr = tid >> 4, n4 = (tid & 15) * 4;
            float4 w = *reinterpret_cast<const float4*>(theta + (size_t)(k0 + kr) * DEMB + bj + n4);
            Bs[kr][n4 + 0] = w.x; Bs[kr][n4 + 1] = w.y;
            Bs[kr][n4 + 2] = w.z; Bs[kr][n4 + 3] = w.w;
        }
        __syncthreads();
        #pragma unroll
        for (int kk = 0; kk < BK; kk++) {
            float a[4], b[4];
            #pragma unroll
            for (int m = 0; m < 4; m++) a[m] = As[kk][ty * 4 + m];
            #pragma unroll
            for (int n = 0; n < 4; n++) b[n] = Bs[kk][tx * 4 + n];
            #pragma unroll
            for (int m = 0; m < 4; m++)
                #pragma unroll
                for (int n = 0; n < 4; n++) acc[m][n] = fmaf(a[m], b[n], acc[m][n]);
        }
        __syncthreads();
    }
    const float de = 0.30151134457776363f;  // 11^-0.5
    #pragma unroll
    for (int m = 0; m < 4; m++) {
        int i = bi + ty * 4 + m;
        float4 o;
        o.x = de * acc[m][0]; o.y = de * acc[m][1];
        o.z = de * acc[m][2]; o.w = de * acc[m][3];
        *reinterpret_cast<float4*>(Xout + (size_t)i * DEMB + bj + tx * 4) = o;
    }
}

// ---------------- 9. E = dv * de * scatter-add of X_out ----------------
__global__ void scatterE(const float* __restrict__ Xout, float* __restrict__ E) {
    int j = blockIdx.x;
    int c = threadIdx.x;
    float v = Xout[(size_t)j * DEMB + c];
    #pragma unroll
    for (int k = 0; k < TK; k++) {
        int r = __ldg(&g_idx[j * TK + k]);
        atomicAdd(E + (size_t)r * DEMB + c, v);
    }
}
__global__ void scaleE(float* __restrict__ E) {
    int t = blockIdx.x * 256 + threadIdx.x;
    const float de = 0.30151134457776363f;
    int i = t >> 8;
    E[t] *= g_dv[i] * de;
}

// ---------------- launch ----------------
extern "C" void kernel_launch(void* const* d_in, const int* in_sizes, int n_in,
                              void* d_out, int out_size) {
    const float* X     = (const float*)d_in[0];
    const float* theta = (const float*)d_in[1];
    float* out  = (float*)d_out;
    float* Xout = out;                                // [8192, 256]
    float* E    = out + (size_t)NN * DEMB;            // [8192, 256]
    float* H    = out + 2 * (size_t)NN * DEMB;        // [8192, 8192]

    static bool attr_set = false;
    if (!attr_set) {
        cudaFuncSetAttribute(dist_mma, cudaFuncAttributeMaxDynamicSharedMemorySize, DSMEM);
        attr_set = true;
    }

    conv_kernel<<<NN, 256>>>(X);
    sq_kernel<<<NN / 8, 256>>>(X);
    dist_mma<<<NTILES, 256, DSMEM>>>();               // upper-tri HMMA -> fp16 D + mirror
    topk_fast<<<NN, 128>>>();
    refine_kernel<<<NN, 128>>>(X);                    // exact-emulated top-11
    zero_cnt<<<NN / 256, 256>>>();
    count_kernel<<<(NN * TK + 255) / 256, 256>>>();
    dv_kernel<<<NN / 256, 256>>>();
    zero_kernel<<<2048, 256>>>((float4*)H, (size_t)NN * NN / 4);
    scatterH<<<(NN * TK + 255) / 256, 256>>>(H);
    gather_kernel<<<NN, 256>>>(X);
    out_gemm<<<dim3(DEMB / 64, NN / 64), 256>>>(theta, Xout);
    zero_kernel<<<256, 256>>>((float4*)E, (size_t)NN * DEMB / 4);
    scatterE<<<NN, 256>>>(Xout, E);
    scaleE<<<NN * DEMB / 256, 256>>>(E);
}